// round 1
// baseline (speedup 1.0000x reference)
#include <cuda_runtime.h>
#include <math.h>

// Problem constants
#define NL  4
#define DM  1024
#define DI  2048
#define DS  16
#define DC  4
#define DTR 64
#define IN_DIM  256
#define OUT_DIM 128
#define BATCH 4096

// ---------------------------------------------------------------------------
// Scratch (no allocations allowed -> __device__ globals)
// ---------------------------------------------------------------------------
__device__ __align__(16) float g_h   [BATCH * DM];        // residual stream
__device__ __align__(16) float g_xz  [BATCH * 2 * DI];    // in_proj output (xc | z)
__device__ __align__(16) float g_xc  [BATCH * DI];        // silu(conv)
__device__ __align__(16) float g_xdbl[BATCH * 96];        // [dt(64) | B(16) | C(16)]
__device__ __align__(16) float g_dtp [BATCH * DI];        // dt pre-softplus
__device__ __align__(16) float g_y   [BATCH * DI];        // gated y
__device__ __align__(16) float g_yo  [BATCH * DM];        // mamba out pre-LN

// ---------------------------------------------------------------------------
// Generic fp32 GEMM:  C[M,N] = A[M,K(lda)] * W[N,K]^T (+ bias[N])
// 128x128 tile, BK=8, 256 threads, 8x8 per-thread microtile.
// Requires: M % 128 == 0, K % 8 == 0 (true for all call sites). N guarded.
// ---------------------------------------------------------------------------
#define BM 128
#define BN 128
#define BKK 8

__global__ __launch_bounds__(256, 2)
void gemm_tn(const float* __restrict__ A, int lda,
             const float* __restrict__ W,
             const float* __restrict__ bias,
             float* __restrict__ C,
             int M, int N, int K)
{
    __shared__ float As[BKK][BM];
    __shared__ float Ws[BKK][BN];

    const int tid = threadIdx.x;
    const int bm = blockIdx.y * BM;
    const int bn = blockIdx.x * BN;
    const int tx = tid & 15;     // N direction (8 cols each)
    const int ty = tid >> 4;     // M direction (8 rows each)

    // tile-load mapping: 128 rows x 8 cols = 1024 floats = 256 float4
    const int lr = tid >> 1;          // row within tile
    const int lc = (tid & 1) * 4;     // col (0 or 4)

    float acc[8][8];
    #pragma unroll
    for (int i = 0; i < 8; i++)
        #pragma unroll
        for (int j = 0; j < 8; j++) acc[i][j] = 0.f;

    for (int k0 = 0; k0 < K; k0 += BKK) {
        // A tile (M always in range)
        float4 av = *(const float4*)&A[(size_t)(bm + lr) * lda + k0 + lc];
        As[lc + 0][lr] = av.x; As[lc + 1][lr] = av.y;
        As[lc + 2][lr] = av.z; As[lc + 3][lr] = av.w;
        // W tile (guard N)
        float4 wv = make_float4(0.f, 0.f, 0.f, 0.f);
        if (bn + lr < N)
            wv = *(const float4*)&W[(size_t)(bn + lr) * K + k0 + lc];
        Ws[lc + 0][lr] = wv.x; Ws[lc + 1][lr] = wv.y;
        Ws[lc + 2][lr] = wv.z; Ws[lc + 3][lr] = wv.w;
        __syncthreads();

        #pragma unroll
        for (int kk = 0; kk < BKK; kk++) {
            float a[8], b[8];
            #pragma unroll
            for (int i = 0; i < 8; i++) a[i] = As[kk][ty * 8 + i];
            #pragma unroll
            for (int j = 0; j < 8; j++) b[j] = Ws[kk][tx * 8 + j];
            #pragma unroll
            for (int i = 0; i < 8; i++)
                #pragma unroll
                for (int j = 0; j < 8; j++)
                    acc[i][j] = fmaf(a[i], b[j], acc[i][j]);
        }
        __syncthreads();
    }

    // epilogue
    float bv[8];
    #pragma unroll
    for (int j = 0; j < 8; j++) {
        int col = bn + tx * 8 + j;
        bv[j] = (bias && col < N) ? bias[col] : 0.f;
    }
    #pragma unroll
    for (int i = 0; i < 8; i++) {
        int row = bm + ty * 8 + i;
        #pragma unroll
        for (int j = 0; j < 8; j++) {
            int col = bn + tx * 8 + j;
            if (col < N) C[(size_t)row * N + col] = acc[i][j] + bv[j];
        }
    }
}

// ---------------------------------------------------------------------------
// Elementwise: xc = silu(conv_b + xz[:, :DI] * conv_w[:, DC-1])
// ---------------------------------------------------------------------------
__global__ void conv_silu_kernel(const float* __restrict__ cw,
                                 const float* __restrict__ cb)
{
    int idx = blockIdx.x * blockDim.x + threadIdx.x;
    if (idx >= BATCH * DI) return;
    int b = idx / DI, e = idx - b * DI;
    float v = g_xz[(size_t)b * (2 * DI) + e];
    float c = cb[e] + v * cw[e * DC + (DC - 1)];
    g_xc[idx] = c / (1.f + expf(-c));
}

// ---------------------------------------------------------------------------
// Per-row: bc = dot(B,C); y = xc * (softplus(dtp+dtb)*bc + Dp) * silu(z)
// one block (256 thr) per batch row
// ---------------------------------------------------------------------------
__global__ void gate_kernel(const float* __restrict__ dtb,
                            const float* __restrict__ Dp)
{
    int b = blockIdx.x;
    int t = threadIdx.x;
    __shared__ float sbc;
    if (t < 32) {
        float p = 0.f;
        if (t < DS)
            p = g_xdbl[(size_t)b * 96 + DTR + t] * g_xdbl[(size_t)b * 96 + DTR + DS + t];
        #pragma unroll
        for (int o = 16; o; o >>= 1) p += __shfl_down_sync(0xffffffffu, p, o);
        if (t == 0) sbc = p;
    }
    __syncthreads();
    float bc = sbc;
    for (int e = t; e < DI; e += 256) {
        float dp = g_dtp[(size_t)b * DI + e] + dtb[e];
        float dt = (dp > 20.f) ? dp : log1pf(expf(dp));
        float xcv = g_xc[(size_t)b * DI + e];
        float zv  = g_xz[(size_t)b * (2 * DI) + DI + e];
        float sz  = zv / (1.f + expf(-zv));
        g_y[(size_t)b * DI + e] = xcv * (dt * bc + Dp[e]) * sz;
    }
}

// ---------------------------------------------------------------------------
// LayerNorm(yo) * g + b, added into residual h. One block (256) per row.
// ---------------------------------------------------------------------------
__global__ void ln_res_kernel(const float* __restrict__ gam,
                              const float* __restrict__ bet)
{
    int b = blockIdx.x;
    int t = threadIdx.x;
    __shared__ float sa[8], sb[8], smu, sinv;
    float s = 0.f, s2 = 0.f;
    for (int d = t; d < DM; d += 256) {
        float v = g_yo[(size_t)b * DM + d];
        s += v; s2 += v * v;
    }
    int lane = t & 31, w = t >> 5;
    #pragma unroll
    for (int o = 16; o; o >>= 1) {
        s  += __shfl_down_sync(0xffffffffu, s,  o);
        s2 += __shfl_down_sync(0xffffffffu, s2, o);
    }
    if (lane == 0) { sa[w] = s; sb[w] = s2; }
    __syncthreads();
    if (w == 0) {
        s  = (lane < 8) ? sa[lane] : 0.f;
        s2 = (lane < 8) ? sb[lane] : 0.f;
        #pragma unroll
        for (int o = 4; o; o >>= 1) {
            s  += __shfl_down_sync(0xffffffffu, s,  o);
            s2 += __shfl_down_sync(0xffffffffu, s2, o);
        }
        if (lane == 0) {
            float mu = s / DM;
            float var = s2 / DM - mu * mu;
            smu = mu;
            sinv = rsqrtf(var + 1e-5f);
        }
    }
    __syncthreads();
    float mu = smu, inv = sinv;
    for (int d = t; d < DM; d += 256) {
        float v = g_yo[(size_t)b * DM + d];
        g_h[(size_t)b * DM + d] += (v - mu) * inv * gam[d] + bet[d];
    }
}

// ---------------------------------------------------------------------------
// Host launcher
// ---------------------------------------------------------------------------
extern "C" void kernel_launch(void* const* d_in, const int* in_sizes, int n_in,
                              void* d_out, int out_size)
{
    const float* x        = (const float*)d_in[0];
    const float* inp_w    = (const float*)d_in[1];
    const float* inp_b    = (const float*)d_in[2];
    const float* in_proj  = (const float*)d_in[3];
    const float* conv_w   = (const float*)d_in[4];
    const float* conv_b   = (const float*)d_in[5];
    const float* xproj_w  = (const float*)d_in[6];
    const float* dt_w     = (const float*)d_in[7];
    const float* dt_b     = (const float*)d_in[8];
    // d_in[9] = A_log : dead with L=1 (multiplies h0 = 0)
    const float* D_param  = (const float*)d_in[10];
    const float* out_w    = (const float*)d_in[11];
    const float* ln_g     = (const float*)d_in[12];
    const float* ln_b     = (const float*)d_in[13];
    const float* outp_w   = (const float*)d_in[14];
    const float* outp_b   = (const float*)d_in[15];
    float* out = (float*)d_out;

    float *p_h, *p_xz, *p_xc, *p_xdbl, *p_dtp, *p_y, *p_yo;
    cudaGetSymbolAddress((void**)&p_h,    g_h);
    cudaGetSymbolAddress((void**)&p_xz,   g_xz);
    cudaGetSymbolAddress((void**)&p_xc,   g_xc);
    cudaGetSymbolAddress((void**)&p_xdbl, g_xdbl);
    cudaGetSymbolAddress((void**)&p_dtp,  g_dtp);
    cudaGetSymbolAddress((void**)&p_y,    g_y);
    cudaGetSymbolAddress((void**)&p_yo,   g_yo);

    dim3 blk(256);
    auto grid = [](int M, int N) { return dim3((N + BN - 1) / BN, (M + BM - 1) / BM); };

    // input projection: h = x @ inp_w^T + inp_b
    gemm_tn<<<grid(BATCH, DM), blk>>>(x, IN_DIM, inp_w, inp_b, p_h, BATCH, DM, IN_DIM);

    for (int l = 0; l < NL; l++) {
        const float* ipw = in_proj + (size_t)l * 2 * DI * DM;
        const float* cw  = conv_w  + (size_t)l * DI * DC;
        const float* cb  = conv_b  + (size_t)l * DI;
        const float* xpw = xproj_w + (size_t)l * (DTR + 2 * DS) * DI;
        const float* dtw = dt_w    + (size_t)l * DI * DTR;
        const float* dtb = dt_b    + (size_t)l * DI;
        const float* Dp  = D_param + (size_t)l * DI;
        const float* ow  = out_w   + (size_t)l * DM * DI;
        const float* lg  = ln_g    + (size_t)l * DM;
        const float* lb  = ln_b    + (size_t)l * DM;

        // xz = h @ in_proj^T            [4096 x 4096] K=1024
        gemm_tn<<<grid(BATCH, 2 * DI), blk>>>(p_h, DM, ipw, nullptr, p_xz, BATCH, 2 * DI, DM);
        // xc = silu(conv_b + xc * conv_w[:, 3])
        conv_silu_kernel<<<(BATCH * DI + 255) / 256, 256>>>(cw, cb);
        // x_dbl = xc @ xproj^T          [4096 x 96] K=2048
        gemm_tn<<<grid(BATCH, DTR + 2 * DS), blk>>>(p_xc, DI, xpw, nullptr, p_xdbl,
                                                    BATCH, DTR + 2 * DS, DI);
        // dt_pre = x_dbl[:, :64] @ dt_w^T  [4096 x 2048] K=64 (lda = 96)
        gemm_tn<<<grid(BATCH, DI), blk>>>(p_xdbl, DTR + 2 * DS, dtw, nullptr, p_dtp,
                                          BATCH, DI, DTR);
        // y = xc * (softplus(dt)*dot(B,C) + D) * silu(z)
        gate_kernel<<<BATCH, 256>>>(dtb, Dp);
        // yo = y @ out_w^T              [4096 x 1024] K=2048
        gemm_tn<<<grid(BATCH, DM), blk>>>(p_y, DI, ow, nullptr, p_yo, BATCH, DM, DI);
        // h += LN(yo)
        ln_res_kernel<<<BATCH, 256>>>(lg, lb);
    }

    // output projection: out = h @ outp_w^T + outp_b
    gemm_tn<<<grid(BATCH, OUT_DIM), blk>>>(p_h, DM, outp_w, outp_b, out,
                                           BATCH, OUT_DIM, DM);
    (void)in_sizes; (void)n_in; (void)out_size;
}

// round 4
// speedup vs baseline: 3.0007x; 3.0007x over previous
#include <cuda_runtime.h>
#include <cuda_bf16.h>
#include <cstdint>
#include <math.h>

// Problem constants
#define NL  4
#define DM  1024
#define DI  2048
#define DS  16
#define DC  4
#define DTR 64
#define IN_DIM  256
#define OUT_DIM 128
#define BATCH 4096
#define XD 96          // DTR + 2*DS

// ---------------------------------------------------------------------------
// Scratch (__device__ globals; no allocations allowed)
// ---------------------------------------------------------------------------
__device__ float g_h   [BATCH * DM];
__device__ float g_xz  [BATCH * 2 * DI];
__device__ float g_xc  [BATCH * DI];
__device__ float g_xdbl[BATCH * XD];
__device__ float g_dtp [BATCH * DI];
__device__ float g_yo  [BATCH * DM];

__device__ __nv_bfloat16 g_x_hi [BATCH * IN_DIM], g_x_lo [BATCH * IN_DIM];
__device__ __nv_bfloat16 g_h_hi [BATCH * DM],     g_h_lo [BATCH * DM];
__device__ __nv_bfloat16 g_xc_hi[BATCH * DI],     g_xc_lo[BATCH * DI];
__device__ __nv_bfloat16 g_xd_hi[BATCH * XD],     g_xd_lo[BATCH * XD];
__device__ __nv_bfloat16 g_y_hi [BATCH * DI],     g_y_lo [BATCH * DI];

__device__ __nv_bfloat16 w_inp_hi[DM * IN_DIM],      w_inp_lo[DM * IN_DIM];
__device__ __nv_bfloat16 w_ip_hi [NL * 2 * DI * DM], w_ip_lo [NL * 2 * DI * DM];
__device__ __nv_bfloat16 w_xp_hi [NL * XD * DI],     w_xp_lo [NL * XD * DI];
__device__ __nv_bfloat16 w_dt_hi [NL * DI * DTR],    w_dt_lo [NL * DI * DTR];
__device__ __nv_bfloat16 w_o_hi  [NL * DM * DI],     w_o_lo  [NL * DM * DI];
__device__ __nv_bfloat16 w_op_hi [OUT_DIM * DM],     w_op_lo [OUT_DIM * DM];

// ---------------------------------------------------------------------------
// PTX helpers (arch-portable: cp.async / ldmatrix / mma.sync)
// ---------------------------------------------------------------------------
__device__ __forceinline__ uint32_t smem_u32(const void* p) {
    uint32_t a;
    asm("{ .reg .u64 t; cvta.to.shared.u64 t, %1; cvt.u32.u64 %0, t; }" : "=r"(a) : "l"(p));
    return a;
}

__device__ __forceinline__ void cp_async16(uint32_t saddr, const void* gaddr, uint32_t sz) {
    asm volatile("cp.async.cg.shared.global [%0], [%1], 16, %2;"
                 :: "r"(saddr), "l"(gaddr), "r"(sz) : "memory");
}
#define CP_COMMIT() asm volatile("cp.async.commit_group;" ::: "memory")
#define CP_WAIT(n)  asm volatile("cp.async.wait_group %0;" :: "n"(n) : "memory")

__device__ __forceinline__ void ldsm4(uint32_t& r0, uint32_t& r1, uint32_t& r2, uint32_t& r3,
                                      uint32_t a) {
    asm volatile("ldmatrix.sync.aligned.m8n8.x4.shared.b16 {%0,%1,%2,%3}, [%4];"
                 : "=r"(r0), "=r"(r1), "=r"(r2), "=r"(r3) : "r"(a));
}

__device__ __forceinline__ void mma_bf16(float* c, const uint32_t* a, const uint32_t* b) {
    asm volatile("mma.sync.aligned.m16n8k16.row.col.f32.bf16.bf16.f32 "
                 "{%0,%1,%2,%3}, {%4,%5,%6,%7}, {%8,%9}, {%0,%1,%2,%3};"
                 : "+f"(c[0]), "+f"(c[1]), "+f"(c[2]), "+f"(c[3])
                 : "r"(a[0]), "r"(a[1]), "r"(a[2]), "r"(a[3]), "r"(b[0]), "r"(b[1]));
}

// ---------------------------------------------------------------------------
// bf16x3 GEMM via mma.sync:
//   C[M=4096, N] = (Ah+Al)[M,K] * (Wh+Wl)[N,K]^T (+bias) ; optional bf16 hi/lo out
// 128x128 CTA tile, BK=32, 8 warps (2m x 4n), warp tile 64x32,
// cp.async double-buffer, ldmatrix fragments.
// ---------------------------------------------------------------------------
#define RS   40                      // smem row stride (elements) -> 80B, conflict-free
#define TILE_B (128 * RS * 2)        // 10240 bytes per operand tile
#define STAGE_B (4 * TILE_B)         // Ah, Al, Bh, Bl
#define GEMM_SMEM (2 * STAGE_B)      // 81920

__global__ __launch_bounds__(256, 2)
void gemm_tc(const __nv_bfloat16* __restrict__ Ah, const __nv_bfloat16* __restrict__ Al, int lda,
             const __nv_bfloat16* __restrict__ Wh, const __nv_bfloat16* __restrict__ Wl,
             const float* __restrict__ bias,
             float* __restrict__ C,
             __nv_bfloat16* __restrict__ Chi, __nv_bfloat16* __restrict__ Clo,
             int N, int K)
{
    extern __shared__ char smem[];
    const uint32_t sbase = smem_u32(smem);

    const int tid  = threadIdx.x;
    const int wid  = tid >> 5;
    const int lane = tid & 31;
    const int bm = blockIdx.y * 128;
    const int bn = blockIdx.x * 128;
    const int wm = (wid >> 2) * 64;       // warp m offset
    const int wn = (wid & 3) * 32;        // warp n offset

    // ---- global->smem stage loader ----
    // per tile: 128 rows x 4 x 16B chunks = 512; thread does idx = tid, tid+256
    const int lrow0 = tid >> 2, lc0 = (tid & 3);           // idx = tid
    const int lrow1 = (tid + 256) >> 2, lc1 = ((tid + 256) & 3);

    auto load_stage = [&](int st, int k0) {
        uint32_t sb = sbase + (st & 1) * STAGE_B;
        // A hi/lo (rows always valid)
        {
            size_t g0 = (size_t)(bm + lrow0) * lda + k0 + lc0 * 8;
            size_t g1 = (size_t)(bm + lrow1) * lda + k0 + lc1 * 8;
            uint32_t s0 = sb + (lrow0 * RS + lc0 * 8) * 2;
            uint32_t s1 = sb + (lrow1 * RS + lc1 * 8) * 2;
            cp_async16(s0,              Ah + g0, 16);
            cp_async16(s1,              Ah + g1, 16);
            cp_async16(s0 + TILE_B,     Al + g0, 16);
            cp_async16(s1 + TILE_B,     Al + g1, 16);
        }
        // B hi/lo (guard rows >= N)
        {
            uint32_t v0 = (bn + lrow0 < N) ? 16u : 0u;
            uint32_t v1 = (bn + lrow1 < N) ? 16u : 0u;
            size_t g0 = (size_t)(bn + lrow0) * K + k0 + lc0 * 8;
            size_t g1 = (size_t)(bn + lrow1) * K + k0 + lc1 * 8;
            uint32_t s0 = sb + 2 * TILE_B + (lrow0 * RS + lc0 * 8) * 2;
            uint32_t s1 = sb + 2 * TILE_B + (lrow1 * RS + lc1 * 8) * 2;
            cp_async16(s0,          Wh + g0, v0);
            cp_async16(s1,          Wh + g1, v1);
            cp_async16(s0 + TILE_B, Wl + g0, v0);
            cp_async16(s1 + TILE_B, Wl + g1, v1);
        }
        CP_COMMIT();
    };

    // ---- ldmatrix lane offsets ----
    const int lm = lane >> 3;   // matrix index 0..3
    const int lr = lane & 7;    // row within matrix
    // A: matrices (m0-7,k0-7),(m8-15,k0-7),(m0-7,k8-15),(m8-15,k8-15)
    const uint32_t aoff = ((uint32_t)((wm + (lm & 1) * 8 + lr) * RS + (lm >> 1) * 8)) * 2;
    // B: matrices (n0-7,k0-7),(n0-7,k8-15),(n8-15,k0-7),(n8-15,k8-15)
    const uint32_t boff = ((uint32_t)((wn + (lm >> 1) * 8 + lr) * RS + (lm & 1) * 8)) * 2;

    float acc[4][4][4];
    #pragma unroll
    for (int i = 0; i < 4; i++)
        #pragma unroll
        for (int j = 0; j < 4; j++)
            #pragma unroll
            for (int q = 0; q < 4; q++) acc[i][j][q] = 0.f;

    const int niter = K >> 5;
    load_stage(0, 0);

    for (int it = 0; it < niter; it++) {
        if (it + 1 < niter) { load_stage(it + 1, (it + 1) << 5); CP_WAIT(1); }
        else                { CP_WAIT(0); }
        __syncthreads();

        uint32_t sb  = sbase + (it & 1) * STAGE_B;
        uint32_t sAh = sb + aoff;
        uint32_t sBh = sb + 2 * TILE_B + boff;

        #pragma unroll
        for (int kk = 0; kk < 2; kk++) {
            uint32_t kb = kk * 32;  // 16 elements * 2 bytes
            // B fragments for all 4 n-tiles, hi and lo
            uint32_t bh[4][2], bl[4][2];
            #pragma unroll
            for (int p = 0; p < 2; p++) {
                ldsm4(bh[2*p][0], bh[2*p][1], bh[2*p+1][0], bh[2*p+1][1],
                      sBh + p * (16 * RS * 2) + kb);
                ldsm4(bl[2*p][0], bl[2*p][1], bl[2*p+1][0], bl[2*p+1][1],
                      sBh + TILE_B + p * (16 * RS * 2) + kb);
            }
            #pragma unroll
            for (int mi = 0; mi < 4; mi++) {
                uint32_t ah[4], al[4];
                ldsm4(ah[0], ah[1], ah[2], ah[3], sAh + mi * (16 * RS * 2) + kb);
                ldsm4(al[0], al[1], al[2], al[3], sAh + TILE_B + mi * (16 * RS * 2) + kb);
                #pragma unroll
                for (int ni = 0; ni < 4; ni++) {
                    mma_bf16(acc[mi][ni], ah, bh[ni]);
                    mma_bf16(acc[mi][ni], ah, bl[ni]);
                    mma_bf16(acc[mi][ni], al, bh[ni]);
                }
            }
        }
        __syncthreads();
    }

    // ---- epilogue ----
    const int g = lane >> 2, t = lane & 3;
    #pragma unroll
    for (int mi = 0; mi < 4; mi++) {
        #pragma unroll
        for (int ni = 0; ni < 4; ni++) {
            int col = bn + wn + ni * 8 + t * 2;
            if (col >= N) continue;
            float b0 = bias ? bias[col]     : 0.f;
            float b1 = bias ? bias[col + 1] : 0.f;
            #pragma unroll
            for (int hrow = 0; hrow < 2; hrow++) {
                int row = bm + wm + mi * 16 + g + hrow * 8;
                float v0 = acc[mi][ni][hrow * 2 + 0] + b0;
                float v1 = acc[mi][ni][hrow * 2 + 1] + b1;
                size_t o = (size_t)row * N + col;
                float2 fv = make_float2(v0, v1);
                *(float2*)(C + o) = fv;
                if (Chi) {
                    __nv_bfloat16 h0 = __float2bfloat16(v0), h1 = __float2bfloat16(v1);
                    __nv_bfloat162 ph = {h0, h1};
                    __nv_bfloat162 pl = {__float2bfloat16(v0 - __bfloat162float(h0)),
                                         __float2bfloat16(v1 - __bfloat162float(h1))};
                    *(__nv_bfloat162*)(Chi + o) = ph;
                    *(__nv_bfloat162*)(Clo + o) = pl;
                }
            }
        }
    }
}

// ---------------------------------------------------------------------------
// fp32 -> bf16 hi/lo split
// ---------------------------------------------------------------------------
__global__ void cvt_kernel(const float* __restrict__ src,
                           __nv_bfloat16* __restrict__ hi,
                           __nv_bfloat16* __restrict__ lo, int n)
{
    int i = blockIdx.x * blockDim.x + threadIdx.x;
    if (i < n) {
        float v = src[i];
        __nv_bfloat16 h = __float2bfloat16(v);
        hi[i] = h;
        lo[i] = __float2bfloat16(v - __bfloat162float(h));
    }
}

// ---------------------------------------------------------------------------
// xc = silu(conv_b + xz[:, :DI] * conv_w[:, DC-1])  (+ hi/lo split)
// ---------------------------------------------------------------------------
__global__ void conv_silu_kernel(const float* __restrict__ cw,
                                 const float* __restrict__ cb)
{
    int idx = blockIdx.x * blockDim.x + threadIdx.x;
    if (idx >= BATCH * DI) return;
    int b = idx / DI, e = idx - b * DI;
    float v = g_xz[(size_t)b * (2 * DI) + e];
    float c = cb[e] + v * cw[e * DC + (DC - 1)];
    float xc = c / (1.f + expf(-c));
    g_xc[idx] = xc;
    __nv_bfloat16 h = __float2bfloat16(xc);
    g_xc_hi[idx] = h;
    g_xc_lo[idx] = __float2bfloat16(xc - __bfloat162float(h));
}

// ---------------------------------------------------------------------------
// y = xc * (softplus(dtp+dtb)*dot(B,C) + Dp) * silu(z)   -> bf16 hi/lo
// ---------------------------------------------------------------------------
__global__ void gate_kernel(const float* __restrict__ dtb,
                            const float* __restrict__ Dp)
{
    int b = blockIdx.x;
    int t = threadIdx.x;
    __shared__ float sbc;
    if (t < 32) {
        float p = 0.f;
        if (t < DS)
            p = g_xdbl[(size_t)b * XD + DTR + t] * g_xdbl[(size_t)b * XD + DTR + DS + t];
        #pragma unroll
        for (int o = 16; o; o >>= 1) p += __shfl_down_sync(0xffffffffu, p, o);
        if (t == 0) sbc = p;
    }
    __syncthreads();
    float bc = sbc;
    for (int e = t; e < DI; e += 256) {
        float dp = g_dtp[(size_t)b * DI + e] + dtb[e];
        float dt = (dp > 20.f) ? dp : log1pf(expf(dp));
        float xcv = g_xc[(size_t)b * DI + e];
        float zv  = g_xz[(size_t)b * (2 * DI) + DI + e];
        float sz  = zv / (1.f + expf(-zv));
        float y = xcv * (dt * bc + Dp[e]) * sz;
        __nv_bfloat16 h = __float2bfloat16(y);
        g_y_hi[(size_t)b * DI + e] = h;
        g_y_lo[(size_t)b * DI + e] = __float2bfloat16(y - __bfloat162float(h));
    }
}

// ---------------------------------------------------------------------------
// h += LN(yo)*g + b ; also re-split h into bf16 hi/lo
// ---------------------------------------------------------------------------
__global__ void ln_res_kernel(const float* __restrict__ gam,
                              const float* __restrict__ bet)
{
    int b = blockIdx.x;
    int t = threadIdx.x;
    __shared__ float sa[8], sbs[8], smu, sinv;
    float s = 0.f, s2 = 0.f;
    for (int d = t; d < DM; d += 256) {
        float v = g_yo[(size_t)b * DM + d];
        s += v; s2 += v * v;
    }
    int lane = t & 31, w = t >> 5;
    #pragma unroll
    for (int o = 16; o; o >>= 1) {
        s  += __shfl_down_sync(0xffffffffu, s,  o);
        s2 += __shfl_down_sync(0xffffffffu, s2, o);
    }
    if (lane == 0) { sa[w] = s; sbs[w] = s2; }
    __syncthreads();
    if (w == 0) {
        s  = (lane < 8) ? sa[lane] : 0.f;
        s2 = (lane < 8) ? sbs[lane] : 0.f;
        #pragma unroll
        for (int o = 4; o; o >>= 1) {
            s  += __shfl_down_sync(0xffffffffu, s,  o);
            s2 += __shfl_down_sync(0xffffffffu, s2, o);
        }
        if (lane == 0) {
            float mu = s / DM;
            float var = s2 / DM - mu * mu;
            smu = mu;
            sinv = rsqrtf(var + 1e-5f);
        }
    }
    __syncthreads();
    float mu = smu, inv = sinv;
    for (int d = t; d < DM; d += 256) {
        size_t o = (size_t)b * DM + d;
        float v = g_yo[o];
        float hv = g_h[o] + (v - mu) * inv * gam[d] + bet[d];
        g_h[o] = hv;
        __nv_bfloat16 hh = __float2bfloat16(hv);
        g_h_hi[o] = hh;
        g_h_lo[o] = __float2bfloat16(hv - __bfloat162float(hh));
    }
}

// ---------------------------------------------------------------------------
// Host launcher
// ---------------------------------------------------------------------------
extern "C" void kernel_launch(void* const* d_in, const int* in_sizes, int n_in,
                              void* d_out, int out_size)
{
    const float* x        = (const float*)d_in[0];
    const float* inp_w    = (const float*)d_in[1];
    const float* inp_b    = (const float*)d_in[2];
    const float* in_proj  = (const float*)d_in[3];
    const float* conv_w   = (const float*)d_in[4];
    const float* conv_b   = (const float*)d_in[5];
    const float* xproj_w  = (const float*)d_in[6];
    const float* dt_w     = (const float*)d_in[7];
    const float* dt_b     = (const float*)d_in[8];
    // d_in[9] = A_log : dead (h0 == 0, single scan step)
    const float* D_param  = (const float*)d_in[10];
    const float* out_w    = (const float*)d_in[11];
    const float* ln_g     = (const float*)d_in[12];
    const float* ln_b     = (const float*)d_in[13];
    const float* outp_w   = (const float*)d_in[14];
    const float* outp_b   = (const float*)d_in[15];
    float* out = (float*)d_out;

    float *p_h, *p_xz, *p_xdbl, *p_dtp, *p_yo;
    cudaGetSymbolAddress((void**)&p_h,    g_h);
    cudaGetSymbolAddress((void**)&p_xz,   g_xz);
    cudaGetSymbolAddress((void**)&p_xdbl, g_xdbl);
    cudaGetSymbolAddress((void**)&p_dtp,  g_dtp);
    cudaGetSymbolAddress((void**)&p_yo,   g_yo);

    __nv_bfloat16 *xh, *xl, *hh, *hl, *xch, *xcl, *xdh, *xdl, *yh, *yl;
    cudaGetSymbolAddress((void**)&xh,  g_x_hi);  cudaGetSymbolAddress((void**)&xl,  g_x_lo);
    cudaGetSymbolAddress((void**)&hh,  g_h_hi);  cudaGetSymbolAddress((void**)&hl,  g_h_lo);
    cudaGetSymbolAddress((void**)&xch, g_xc_hi); cudaGetSymbolAddress((void**)&xcl, g_xc_lo);
    cudaGetSymbolAddress((void**)&xdh, g_xd_hi); cudaGetSymbolAddress((void**)&xdl, g_xd_lo);
    cudaGetSymbolAddress((void**)&yh,  g_y_hi);  cudaGetSymbolAddress((void**)&yl,  g_y_lo);

    __nv_bfloat16 *wih, *wil, *wph, *wpl, *wxh, *wxl, *wdh, *wdl, *woh, *wol, *wqh, *wql;
    cudaGetSymbolAddress((void**)&wih, w_inp_hi); cudaGetSymbolAddress((void**)&wil, w_inp_lo);
    cudaGetSymbolAddress((void**)&wph, w_ip_hi);  cudaGetSymbolAddress((void**)&wpl, w_ip_lo);
    cudaGetSymbolAddress((void**)&wxh, w_xp_hi);  cudaGetSymbolAddress((void**)&wxl, w_xp_lo);
    cudaGetSymbolAddress((void**)&wdh, w_dt_hi);  cudaGetSymbolAddress((void**)&wdl, w_dt_lo);
    cudaGetSymbolAddress((void**)&woh, w_o_hi);   cudaGetSymbolAddress((void**)&wol, w_o_lo);
    cudaGetSymbolAddress((void**)&wqh, w_op_hi);  cudaGetSymbolAddress((void**)&wql, w_op_lo);

    cudaFuncSetAttribute(gemm_tc, cudaFuncAttributeMaxDynamicSharedMemorySize, GEMM_SMEM);

    auto cvt = [](const float* s, __nv_bfloat16* h, __nv_bfloat16* l, int n) {
        cvt_kernel<<<(n + 255) / 256, 256>>>(s, h, l, n);
    };
    cvt(x,       xh,  xl,  BATCH * IN_DIM);
    cvt(inp_w,   wih, wil, DM * IN_DIM);
    cvt(in_proj, wph, wpl, NL * 2 * DI * DM);
    cvt(xproj_w, wxh, wxl, NL * XD * DI);
    cvt(dt_w,    wdh, wdl, NL * DI * DTR);
    cvt(out_w,   woh, wol, NL * DM * DI);
    cvt(outp_w,  wqh, wql, OUT_DIM * DM);

    auto grid = [](int N) { return dim3((N + 127) / 128, BATCH / 128); };
    dim3 blk(256);

    // h = x @ inp_w^T + inp_b (emits hi/lo)
    gemm_tc<<<grid(DM), blk, GEMM_SMEM>>>(xh, xl, IN_DIM, wih, wil, inp_b,
                                          p_h, hh, hl, DM, IN_DIM);

    for (int l = 0; l < NL; l++) {
        const __nv_bfloat16* iph = wph + (size_t)l * 2 * DI * DM;
        const __nv_bfloat16* ipl = wpl + (size_t)l * 2 * DI * DM;
        const __nv_bfloat16* xph = wxh + (size_t)l * XD * DI;
        const __nv_bfloat16* xpl = wxl + (size_t)l * XD * DI;
        const __nv_bfloat16* dth = wdh + (size_t)l * DI * DTR;
        const __nv_bfloat16* dtl = wdl + (size_t)l * DI * DTR;
        const __nv_bfloat16* oh  = woh + (size_t)l * DM * DI;
        const __nv_bfloat16* ol  = wol + (size_t)l * DM * DI;
        const float* cw  = conv_w  + (size_t)l * DI * DC;
        const float* cb  = conv_b  + (size_t)l * DI;
        const float* dtb = dt_b    + (size_t)l * DI;
        const float* Dp  = D_param + (size_t)l * DI;
        const float* lg  = ln_g    + (size_t)l * DM;
        const float* lb  = ln_b    + (size_t)l * DM;

        // xz = h @ in_proj^T   [4096 x 4096], K=1024
        gemm_tc<<<grid(2 * DI), blk, GEMM_SMEM>>>(hh, hl, DM, iph, ipl, nullptr,
                                                  p_xz, nullptr, nullptr, 2 * DI, DM);
        conv_silu_kernel<<<(BATCH * DI + 255) / 256, 256>>>(cw, cb);
        // x_dbl = xc @ xproj^T  [4096 x 96], K=2048 (emits hi/lo)
        gemm_tc<<<grid(XD), blk, GEMM_SMEM>>>(xch, xcl, DI, xph, xpl, nullptr,
                                              p_xdbl, xdh, xdl, XD, DI);
        // dt_pre = x_dbl[:, :64] @ dt_w^T  [4096 x 2048], K=64 (lda=96)
        gemm_tc<<<grid(DI), blk, GEMM_SMEM>>>(xdh, xdl, XD, dth, dtl, nullptr,
                                              p_dtp, nullptr, nullptr, DI, DTR);
        gate_kernel<<<BATCH, 256>>>(dtb, Dp);
        // yo = y @ out_w^T  [4096 x 1024], K=2048
        gemm_tc<<<grid(DM), blk, GEMM_SMEM>>>(yh, yl, DI, oh, ol, nullptr,
                                              p_yo, nullptr, nullptr, DM, DI);
        ln_res_kernel<<<BATCH, 256>>>(lg, lb);
    }

    // out = h @ outp_w^T + outp_b
    gemm_tc<<<grid(OUT_DIM), blk, GEMM_SMEM>>>(hh, hl, DM, wqh, wql, outp_b,
                                               out, nullptr, nullptr, OUT_DIM, DM);
    (void)in_sizes; (void)n_in; (void)out_size;
}

// round 6
// speedup vs baseline: 3.8156x; 1.2716x over previous
#include <cuda_runtime.h>
#include <cuda_bf16.h>
#include <cstdint>
#include <math.h>

// Problem constants
#define NL  4
#define DM  1024
#define DI  2048
#define DS  16
#define DC  4
#define DTR 64
#define IN_DIM  256
#define OUT_DIM 128
#define BATCH 4096
#define XD 96          // DTR + 2*DS

// ---------------------------------------------------------------------------
// fp32 scratch
// ---------------------------------------------------------------------------
__device__ float g_h   [BATCH * DM];
__device__ float g_xz  [BATCH * 2 * DI];
__device__ float g_xc  [BATCH * DI];
__device__ float g_xdbl[BATCH * XD];
__device__ float g_dtp [BATCH * DI];
__device__ float g_yo  [BATCH * DM];

// ---------------------------------------------------------------------------
// Tiled bf16 operands. Tile = 128 rows x 64 cols = 8192 elems = 16KB,
// SW128-swizzled internally, tiles contiguous: (rb*KT + kb)*8192 elems.
// ---------------------------------------------------------------------------
__device__ __align__(1024) __nv_bfloat16 t_x_hi [BATCH * IN_DIM], t_x_lo [BATCH * IN_DIM];
__device__ __align__(1024) __nv_bfloat16 t_h_hi [BATCH * DM],     t_h_lo [BATCH * DM];
__device__ __align__(1024) __nv_bfloat16 t_xc_hi[BATCH * DI],     t_xc_lo[BATCH * DI];
__device__ __align__(1024) __nv_bfloat16 t_xd_hi[BATCH * 128],    t_xd_lo[BATCH * 128];   // XD padded to 128
__device__ __align__(1024) __nv_bfloat16 t_y_hi [BATCH * DI],     t_y_lo [BATCH * DI];

__device__ __align__(1024) __nv_bfloat16 t_wi_hi[DM * IN_DIM],       t_wi_lo[DM * IN_DIM];
__device__ __align__(1024) __nv_bfloat16 t_wp_hi[NL * 2 * DI * DM],  t_wp_lo[NL * 2 * DI * DM];
__device__ __align__(1024) __nv_bfloat16 t_wx_hi[NL * 128 * DI],     t_wx_lo[NL * 128 * DI];  // rows padded 96->128
__device__ __align__(1024) __nv_bfloat16 t_wd_hi[NL * DI * DTR],     t_wd_lo[NL * DI * DTR];
__device__ __align__(1024) __nv_bfloat16 t_wo_hi[NL * DM * DI],      t_wo_lo[NL * DM * DI];
__device__ __align__(1024) __nv_bfloat16 t_wq_hi[OUT_DIM * DM],      t_wq_lo[OUT_DIM * DM];

// ---------------------------------------------------------------------------
// Tiled addressing: element (row, col) of a [R, K] matrix, KT = Kpad/64.
// inner bytes = (row&127)*128 + (((col&63)*2) ^ ((row&7)<<4))   (SW128)
// ---------------------------------------------------------------------------
__device__ __forceinline__ size_t tiled_off(int row, int col, int KT) {
    size_t tile = (size_t)((row >> 7) * KT + (col >> 6));
    uint32_t inner = (uint32_t)((row & 127) * 128)
                   + (((uint32_t)((col & 63) * 2)) ^ ((uint32_t)(row & 7) << 4));
    return tile * 8192 + (inner >> 1);
}

// ---------------------------------------------------------------------------
// PTX helpers
// ---------------------------------------------------------------------------
__device__ __forceinline__ uint32_t smem_u32(const void* p) {
    uint32_t a;
    asm("{ .reg .u64 t; cvta.to.shared.u64 t, %1; cvt.u32.u64 %0, t; }" : "=r"(a) : "l"(p));
    return a;
}
#define MBARRIER_INIT(a, c) \
    asm volatile("mbarrier.init.shared.b64 [%0], %1;" :: "r"((uint32_t)(a)), "r"((uint32_t)(c)) : "memory")
#define MBAR_EXPECT(a, n) \
    asm volatile("mbarrier.arrive.expect_tx.shared.b64 _, [%0], %1;" :: "r"((uint32_t)(a)), "r"((uint32_t)(n)) : "memory")
#define CP_BULK(sdst, gsrc, nbytes, bar) \
    asm volatile("cp.async.bulk.shared::cta.global.mbarrier::complete_tx::bytes [%0], [%1], %2, [%3];" \
                 :: "r"((uint32_t)(sdst)), "l"(gsrc), "r"((uint32_t)(nbytes)), "r"((uint32_t)(bar)) : "memory")
#define MBARRIER_WAIT_PARITY(mbar_smem_addr, phase_parity) do { \
    uint32_t _mbar = (uint32_t)(mbar_smem_addr); \
    uint32_t _parity = (uint32_t)(phase_parity); \
    uint32_t _done; \
    asm volatile("{\n\t.reg .pred p;\n\t" \
        "mbarrier.try_wait.parity.acquire.cta.shared::cta.b64 p, [%1], %2;\n\t" \
        "selp.b32 %0, 1, 0, p;\n\t}" : "=r"(_done) : "r"(_mbar), "r"(_parity) : "memory"); \
    if (!_done) { \
        asm volatile("{\n\t.reg .pred P1;\n\t" \
            "WAIT_LOOP_%=:\n\t" \
            "mbarrier.try_wait.parity.acquire.cta.shared::cta.b64 P1, [%0], %1, 0x989680;\n\t" \
            "@P1 bra.uni WAIT_DONE_%=;\n\t" \
            "bra.uni WAIT_LOOP_%=;\n\t" \
            "WAIT_DONE_%=:\n\t}" :: "r"(_mbar), "r"(_parity) : "memory"); \
    } \
} while (0)

__device__ __forceinline__ void ldsm4(uint32_t& r0, uint32_t& r1, uint32_t& r2, uint32_t& r3,
                                      uint32_t a) {
    asm volatile("ldmatrix.sync.aligned.m8n8.x4.shared.b16 {%0,%1,%2,%3}, [%4];"
                 : "=r"(r0), "=r"(r1), "=r"(r2), "=r"(r3) : "r"(a));
}
__device__ __forceinline__ void mma_bf16(float* c, const uint32_t* a, const uint32_t* b) {
    asm volatile("mma.sync.aligned.m16n8k16.row.col.f32.bf16.bf16.f32 "
                 "{%0,%1,%2,%3}, {%4,%5,%6,%7}, {%8,%9}, {%0,%1,%2,%3};"
                 : "+f"(c[0]), "+f"(c[1]), "+f"(c[2]), "+f"(c[3])
                 : "r"(a[0]), "r"(a[1]), "r"(a[2]), "r"(a[3]), "r"(b[0]), "r"(b[1]));
}

__device__ __forceinline__ uint32_t pack_bf2(float a, float b) {
    __nv_bfloat162 p = {__float2bfloat16(a), __float2bfloat16(b)};
    return *(uint32_t*)&p;
}

// ---------------------------------------------------------------------------
// bf16x3 GEMM, bulk-copy 3-stage pipeline.
// CTA tile 128x128, BK=64, 256 threads (8 warps, warp tile 64x32).
// A,W operands in tiled+swizzled global layout (hi & lo separate).
// ---------------------------------------------------------------------------
#define TILE_BYTES 16384
#define STAGE_BYTES (4 * TILE_BYTES)
#define NSTAGE 3
#define GEMM_SMEM (NSTAGE * STAGE_BYTES + 64)   // 196672

__global__ __launch_bounds__(256, 1)
void gemm_tc(const __nv_bfloat16* __restrict__ Ah, const __nv_bfloat16* __restrict__ Al, int KTa,
             const __nv_bfloat16* __restrict__ Wh, const __nv_bfloat16* __restrict__ Wl, int KTb,
             int niter,
             const float* __restrict__ bias,
             float* __restrict__ C, int N,
             __nv_bfloat16* __restrict__ Chi, __nv_bfloat16* __restrict__ Clo, int NT)
{
    extern __shared__ char smem[];
    const uint32_t sbase = smem_u32(smem);
    const uint32_t sbar  = sbase + NSTAGE * STAGE_BYTES;

    const int tid  = threadIdx.x;
    const int wid  = tid >> 5;
    const int lane = tid & 31;
    const int rbA = blockIdx.y;
    const int rbB = blockIdx.x;

    if (tid == 0) {
        MBARRIER_INIT(sbar + 0, 1);
        MBARRIER_INIT(sbar + 8, 1);
        MBARRIER_INIT(sbar + 16, 1);
        asm volatile("fence.proxy.async.shared::cta;" ::: "memory");
    }
    __syncthreads();

    const char* pAh = (const char*)Ah;
    const char* pAl = (const char*)Al;
    const char* pWh = (const char*)Wh;
    const char* pWl = (const char*)Wl;

    auto issue = [&](int kb, int s) {
        uint32_t st = sbase + s * STAGE_BYTES;
        uint32_t bar = sbar + s * 8;
        MBAR_EXPECT(bar, 4 * TILE_BYTES);
        size_t oa = ((size_t)(rbA * KTa + kb)) << 14;
        size_t ob = ((size_t)(rbB * KTb + kb)) << 14;
        CP_BULK(st,                  pAh + oa, TILE_BYTES, bar);
        CP_BULK(st + TILE_BYTES,     pAl + oa, TILE_BYTES, bar);
        CP_BULK(st + 2 * TILE_BYTES, pWh + ob, TILE_BYTES, bar);
        CP_BULK(st + 3 * TILE_BYTES, pWl + ob, TILE_BYTES, bar);
    };

    if (tid == 0) {
        #pragma unroll
        for (int s = 0; s < NSTAGE; s++)
            if (s < niter) issue(s, s);
    }

    // ldmatrix lane constants
    const int lm = lane >> 3;     // matrix index 0..3
    const int lr = lane & 7;      // row within 8x8 matrix
    const int wm = (wid >> 2) * 64;
    const int wn = (wid & 3) * 32;
    const uint32_t xmask = (uint32_t)lr << 4;               // SW128 chunk mask
    const uint32_t arow = (uint32_t)(wm + (lm & 1) * 8 + lr) * 128;
    const uint32_t aseg = (uint32_t)(lm >> 1) * 16;
    const uint32_t brow = (uint32_t)(wn + (lm >> 1) * 8 + lr) * 128;
    const uint32_t bseg = (uint32_t)(lm & 1) * 16;

    float acc[4][4][4];
    #pragma unroll
    for (int i = 0; i < 4; i++)
        #pragma unroll
        for (int j = 0; j < 4; j++)
            #pragma unroll
            for (int q = 0; q < 4; q++) acc[i][j][q] = 0.f;

    for (int kb = 0; kb < niter; kb++) {
        int s = kb % 3;
        MBARRIER_WAIT_PARITY(sbar + s * 8, (kb / 3) & 1);
        uint32_t st  = sbase + s * STAGE_BYTES;
        uint32_t sAh = st;
        uint32_t sAl = st + TILE_BYTES;
        uint32_t sBh = st + 2 * TILE_BYTES;
        uint32_t sBl = st + 3 * TILE_BYTES;

        #pragma unroll
        for (int kk = 0; kk < 4; kk++) {
            uint32_t ka = ((uint32_t)(kk * 32) + aseg) ^ xmask;
            uint32_t kbo = ((uint32_t)(kk * 32) + bseg) ^ xmask;
            uint32_t bh[4][2], bl[4][2];
            #pragma unroll
            for (int p = 0; p < 2; p++) {
                ldsm4(bh[2*p][0], bh[2*p][1], bh[2*p+1][0], bh[2*p+1][1],
                      sBh + brow + p * 2048 + kbo);
                ldsm4(bl[2*p][0], bl[2*p][1], bl[2*p+1][0], bl[2*p+1][1],
                      sBl + brow + p * 2048 + kbo);
            }
            #pragma unroll
            for (int mi = 0; mi < 4; mi++) {
                uint32_t ah[4], al[4];
                ldsm4(ah[0], ah[1], ah[2], ah[3], sAh + arow + mi * 2048 + ka);
                ldsm4(al[0], al[1], al[2], al[3], sAl + arow + mi * 2048 + ka);
                #pragma unroll
                for (int ni = 0; ni < 4; ni++) {
                    mma_bf16(acc[mi][ni], ah, bh[ni]);
                    mma_bf16(acc[mi][ni], ah, bl[ni]);
                    mma_bf16(acc[mi][ni], al, bh[ni]);
                }
            }
        }
        __syncthreads();
        if (tid == 0 && kb + NSTAGE < niter) issue(kb + NSTAGE, s);
    }

    // ---- epilogue ----
    const int g = lane >> 2, t4 = lane & 3;
    const int bm = rbA * 128, bn = rbB * 128;
    #pragma unroll
    for (int mi = 0; mi < 4; mi++) {
        #pragma unroll
        for (int ni = 0; ni < 4; ni++) {
            int col = bn + wn + ni * 8 + t4 * 2;
            float b0 = 0.f, b1 = 0.f;
            if (bias && col < N) { b0 = bias[col]; b1 = bias[col + 1]; }
            #pragma unroll
            for (int hrow = 0; hrow < 2; hrow++) {
                int row = bm + wm + mi * 16 + g + hrow * 8;
                float v0 = acc[mi][ni][hrow * 2 + 0] + b0;
                float v1 = acc[mi][ni][hrow * 2 + 1] + b1;
                if (col < N)
                    *(float2*)(C + (size_t)row * N + col) = make_float2(v0, v1);
                if (Chi) {
                    size_t to = tiled_off(row, col, NT);
                    __nv_bfloat16 h0 = __float2bfloat16(v0), h1 = __float2bfloat16(v1);
                    __nv_bfloat162 ph = {h0, h1};
                    __nv_bfloat162 pl = {__float2bfloat16(v0 - __bfloat162float(h0)),
                                         __float2bfloat16(v1 - __bfloat162float(h1))};
                    *(__nv_bfloat162*)(Chi + to) = ph;
                    *(__nv_bfloat162*)(Clo + to) = pl;
                }
            }
        }
    }
}

// ---------------------------------------------------------------------------
// fp32 [R,K] -> tiled+swizzled bf16 hi/lo. One thread per 8-col chunk.
// ---------------------------------------------------------------------------
__global__ void cvt_tiled(const float* __restrict__ src,
                          __nv_bfloat16* __restrict__ hi,
                          __nv_bfloat16* __restrict__ lo,
                          int R, int k8, int KT)
{
    int idx = blockIdx.x * 256 + threadIdx.x;
    if (idx >= R * k8) return;
    int row = idx / k8;
    int k = (idx - row * k8) * 8;
    const float4* s = (const float4*)(src + (size_t)row * (k8 * 8) + k);
    float4 v0 = s[0], v1 = s[1];
    float f[8] = {v0.x, v0.y, v0.z, v0.w, v1.x, v1.y, v1.z, v1.w};
    uint32_t ph[4], pl[4];
    #pragma unroll
    for (int j = 0; j < 4; j++) {
        float a = f[2*j], b = f[2*j+1];
        __nv_bfloat16 ha = __float2bfloat16(a), hb = __float2bfloat16(b);
        __nv_bfloat162 vh = {ha, hb};
        __nv_bfloat162 vl = {__float2bfloat16(a - __bfloat162float(ha)),
                             __float2bfloat16(b - __bfloat162float(hb))};
        ph[j] = *(uint32_t*)&vh;
        pl[j] = *(uint32_t*)&vl;
    }
    size_t to = tiled_off(row, k, KT);
    *(uint4*)(hi + to) = make_uint4(ph[0], ph[1], ph[2], ph[3]);
    *(uint4*)(lo + to) = make_uint4(pl[0], pl[1], pl[2], pl[3]);
}

// ---------------------------------------------------------------------------
// xc = silu(conv_b + xz[:, :DI] * conv_w[:, DC-1]); fp32 + tiled hi/lo
// one thread per 8-col chunk: idx -> (b, c8)
// ---------------------------------------------------------------------------
__global__ void conv_silu_kernel(const float* __restrict__ cw,
                                 const float* __restrict__ cb)
{
    int idx = blockIdx.x * 256 + threadIdx.x;       // BATCH*256 total
    int b = idx >> 8;
    int e = (idx & 255) * 8;
    const float4* s = (const float4*)(g_xz + (size_t)b * (2 * DI) + e);
    float4 v0 = s[0], v1 = s[1];
    float f[8] = {v0.x, v0.y, v0.z, v0.w, v1.x, v1.y, v1.z, v1.w};
    float r[8];
    #pragma unroll
    for (int j = 0; j < 8; j++) {
        float c = cb[e + j] + f[j] * cw[(e + j) * DC + (DC - 1)];
        r[j] = c / (1.f + expf(-c));
    }
    float4* d = (float4*)(g_xc + (size_t)b * DI + e);
    d[0] = make_float4(r[0], r[1], r[2], r[3]);
    d[1] = make_float4(r[4], r[5], r[6], r[7]);
    uint32_t ph[4], pl[4];
    #pragma unroll
    for (int j = 0; j < 4; j++) {
        __nv_bfloat16 ha = __float2bfloat16(r[2*j]), hb = __float2bfloat16(r[2*j+1]);
        __nv_bfloat162 vh = {ha, hb};
        __nv_bfloat162 vl = {__float2bfloat16(r[2*j]   - __bfloat162float(ha)),
                             __float2bfloat16(r[2*j+1] - __bfloat162float(hb))};
        ph[j] = *(uint32_t*)&vh; pl[j] = *(uint32_t*)&vl;
    }
    size_t to = tiled_off(b, e, DI / 64);
    *(uint4*)(t_xc_hi + to) = make_uint4(ph[0], ph[1], ph[2], ph[3]);
    *(uint4*)(t_xc_lo + to) = make_uint4(pl[0], pl[1], pl[2], pl[3]);
}

// ---------------------------------------------------------------------------
// y = xc * (softplus(dtp+dtb)*dot(B,C) + Dp) * silu(z) -> tiled hi/lo
// one block per batch row, thread handles 8 consecutive e
// ---------------------------------------------------------------------------
__global__ void gate_kernel(const float* __restrict__ dtb,
                            const float* __restrict__ Dp)
{
    int b = blockIdx.x;
    int t = threadIdx.x;
    __shared__ float sbc;
    if (t < 32) {
        float p = 0.f;
        if (t < DS)
            p = g_xdbl[(size_t)b * XD + DTR + t] * g_xdbl[(size_t)b * XD + DTR + DS + t];
        #pragma unroll
        for (int o = 16; o; o >>= 1) p += __shfl_down_sync(0xffffffffu, p, o);
        if (t == 0) sbc = p;
    }
    __syncthreads();
    float bc = sbc;
    int e = t * 8;
    const float4* sd = (const float4*)(g_dtp + (size_t)b * DI + e);
    const float4* sx = (const float4*)(g_xc  + (size_t)b * DI + e);
    const float4* sz = (const float4*)(g_xz  + (size_t)b * (2 * DI) + DI + e);
    float4 d0 = sd[0], d1 = sd[1], x0 = sx[0], x1 = sx[1], z0 = sz[0], z1 = sz[1];
    float dv[8] = {d0.x,d0.y,d0.z,d0.w,d1.x,d1.y,d1.z,d1.w};
    float xv[8] = {x0.x,x0.y,x0.z,x0.w,x1.x,x1.y,x1.z,x1.w};
    float zv[8] = {z0.x,z0.y,z0.z,z0.w,z1.x,z1.y,z1.z,z1.w};
    float y[8];
    #pragma unroll
    for (int j = 0; j < 8; j++) {
        float dp = dv[j] + dtb[e + j];
        float dt = (dp > 20.f) ? dp : log1pf(expf(dp));
        float sz2 = zv[j] / (1.f + expf(-zv[j]));
        y[j] = xv[j] * (dt * bc + Dp[e + j]) * sz2;
    }
    uint32_t ph[4], pl[4];
    #pragma unroll
    for (int j = 0; j < 4; j++) {
        __nv_bfloat16 ha = __float2bfloat16(y[2*j]), hb = __float2bfloat16(y[2*j+1]);
        __nv_bfloat162 vh = {ha, hb};
        __nv_bfloat162 vl = {__float2bfloat16(y[2*j]   - __bfloat162float(ha)),
                             __float2bfloat16(y[2*j+1] - __bfloat162float(hb))};
        ph[j] = *(uint32_t*)&vh; pl[j] = *(uint32_t*)&vl;
    }
    size_t to = tiled_off(b, e, DI / 64);
    *(uint4*)(t_y_hi + to) = make_uint4(ph[0], ph[1], ph[2], ph[3]);
    *(uint4*)(t_y_lo + to) = make_uint4(pl[0], pl[1], pl[2], pl[3]);
}

// ---------------------------------------------------------------------------
// h += LN(yo)*g + b; fp32 h + tiled hi/lo. One block per row, 4 elems/thread.
// ---------------------------------------------------------------------------
__global__ void ln_res_kernel(const float* __restrict__ gam,
                              const float* __restrict__ bet)
{
    int b = blockIdx.x;
    int t = threadIdx.x;
    __shared__ float sa[8], sbs[8], smu, sinv;
    int d = t * 4;
    float4 v4 = *(const float4*)(g_yo + (size_t)b * DM + d);
    float vv[4] = {v4.x, v4.y, v4.z, v4.w};
    float s = vv[0] + vv[1] + vv[2] + vv[3];
    float s2 = vv[0]*vv[0] + vv[1]*vv[1] + vv[2]*vv[2] + vv[3]*vv[3];
    int lane = t & 31, w = t >> 5;
    #pragma unroll
    for (int o = 16; o; o >>= 1) {
        s  += __shfl_down_sync(0xffffffffu, s,  o);
        s2 += __shfl_down_sync(0xffffffffu, s2, o);
    }
    if (lane == 0) { sa[w] = s; sbs[w] = s2; }
    __syncthreads();
    if (w == 0) {
        s  = (lane < 8) ? sa[lane] : 0.f;
        s2 = (lane < 8) ? sbs[lane] : 0.f;
        #pragma unroll
        for (int o = 4; o; o >>= 1) {
            s  += __shfl_down_sync(0xffffffffu, s,  o);
            s2 += __shfl_down_sync(0xffffffffu, s2, o);
        }
        if (lane == 0) {
            float mu = s / DM;
            float var = s2 / DM - mu * mu;
            smu = mu;
            sinv = rsqrtf(var + 1e-5f);
        }
    }
    __syncthreads();
    float mu = smu, inv = sinv;
    float hv[4];
    #pragma unroll
    for (int j = 0; j < 4; j++) {
        size_t o = (size_t)b * DM + d + j;
        hv[j] = g_h[o] + (vv[j] - mu) * inv * gam[d + j] + bet[d + j];
        g_h[o] = hv[j];
    }
    uint32_t ph[2], pl[2];
    #pragma unroll
    for (int j = 0; j < 2; j++) {
        __nv_bfloat16 ha = __float2bfloat16(hv[2*j]), hb = __float2bfloat16(hv[2*j+1]);
        __nv_bfloat162 vh = {ha, hb};
        __nv_bfloat162 vl = {__float2bfloat16(hv[2*j]   - __bfloat162float(ha)),
                             __float2bfloat16(hv[2*j+1] - __bfloat162float(hb))};
        ph[j] = *(uint32_t*)&vh; pl[j] = *(uint32_t*)&vl;
    }
    size_t to = tiled_off(b, d, DM / 64);
    *(uint2*)(t_h_hi + to) = make_uint2(ph[0], ph[1]);
    *(uint2*)(t_h_lo + to) = make_uint2(pl[0], pl[1]);
}

// ---------------------------------------------------------------------------
// Host launcher
// ---------------------------------------------------------------------------
extern "C" void kernel_launch(void* const* d_in, const int* in_sizes, int n_in,
                              void* d_out, int out_size)
{
    const float* x        = (const float*)d_in[0];
    const float* inp_w    = (const float*)d_in[1];
    const float* inp_b    = (const float*)d_in[2];
    const float* in_proj  = (const float*)d_in[3];
    const float* conv_w   = (const float*)d_in[4];
    const float* conv_b   = (const float*)d_in[5];
    const float* xproj_w  = (const float*)d_in[6];
    const float* dt_w     = (const float*)d_in[7];
    const float* dt_b     = (const float*)d_in[8];
    // d_in[9] = A_log : dead (h0 == 0, single scan step)
    const float* D_param  = (const float*)d_in[10];
    const float* out_w    = (const float*)d_in[11];
    const float* ln_g     = (const float*)d_in[12];
    const float* ln_b     = (const float*)d_in[13];
    const float* outp_w   = (const float*)d_in[14];
    const float* outp_b   = (const float*)d_in[15];
    float* out = (float*)d_out;

    float *p_h, *p_xz, *p_xdbl, *p_dtp, *p_yo;
    cudaGetSymbolAddress((void**)&p_h,    g_h);
    cudaGetSymbolAddress((void**)&p_xz,   g_xz);
    cudaGetSymbolAddress((void**)&p_xdbl, g_xdbl);
    cudaGetSymbolAddress((void**)&p_dtp,  g_dtp);
    cudaGetSymbolAddress((void**)&p_yo,   g_yo);

    __nv_bfloat16 *xh, *xl, *hh, *hl, *xch, *xcl, *xdh, *xdl, *yh, *yl;
    cudaGetSymbolAddress((void**)&xh,  t_x_hi);  cudaGetSymbolAddress((void**)&xl,  t_x_lo);
    cudaGetSymbolAddress((void**)&hh,  t_h_hi);  cudaGetSymbolAddress((void**)&hl,  t_h_lo);
    cudaGetSymbolAddress((void**)&xch, t_xc_hi); cudaGetSymbolAddress((void**)&xcl, t_xc_lo);
    cudaGetSymbolAddress((void**)&xdh, t_xd_hi); cudaGetSymbolAddress((void**)&xdl, t_xd_lo);
    cudaGetSymbolAddress((void**)&yh,  t_y_hi);  cudaGetSymbolAddress((void**)&yl,  t_y_lo);

    __nv_bfloat16 *wih, *wil, *wph, *wpl, *wxh, *wxl, *wdh, *wdl, *woh, *wol, *wqh, *wql;
    cudaGetSymbolAddress((void**)&wih, t_wi_hi); cudaGetSymbolAddress((void**)&wil, t_wi_lo);
    cudaGetSymbolAddress((void**)&wph, t_wp_hi); cudaGetSymbolAddress((void**)&wpl, t_wp_lo);
    cudaGetSymbolAddress((void**)&wxh, t_wx_hi); cudaGetSymbolAddress((void**)&wxl, t_wx_lo);
    cudaGetSymbolAddress((void**)&wdh, t_wd_hi); cudaGetSymbolAddress((void**)&wdl, t_wd_lo);
    cudaGetSymbolAddress((void**)&woh, t_wo_hi); cudaGetSymbolAddress((void**)&wol, t_wo_lo);
    cudaGetSymbolAddress((void**)&wqh, t_wq_hi); cudaGetSymbolAddress((void**)&wql, t_wq_lo);

    cudaFuncSetAttribute(gemm_tc, cudaFuncAttributeMaxDynamicSharedMemorySize, GEMM_SMEM);

    auto cvt = [](const float* s, __nv_bfloat16* h, __nv_bfloat16* l, int R, int K) {
        int n = R * (K / 8);
        cvt_tiled<<<(n + 255) / 256, 256>>>(s, h, l, R, K / 8, K / 64);
    };
    // conversions (deterministic every call)
    cvt(x,       xh,  xl,  BATCH, IN_DIM);
    cvt(inp_w,   wih, wil, DM, IN_DIM);
    cvt(in_proj, wph, wpl, NL * 2 * DI, DM);
    for (int l = 0; l < NL; l++)   // padded rows 96->128 per layer
        cvt(xproj_w + (size_t)l * XD * DI, wxh + (size_t)l * 128 * DI,
            wxl + (size_t)l * 128 * DI, XD, DI);
    cvt(dt_w,    wdh, wdl, NL * DI, DTR);
    cvt(out_w,   woh, wol, NL * DM, DI);
    cvt(outp_w,  wqh, wql, OUT_DIM, DM);

    dim3 blk(256);

    // h = x @ inp_w^T + inp_b  (emits tiled hi/lo)
    gemm_tc<<<dim3(DM/128, BATCH/128), blk, GEMM_SMEM>>>(
        xh, xl, IN_DIM/64, wih, wil, IN_DIM/64, IN_DIM/64,
        inp_b, p_h, DM, hh, hl, DM/64);

    for (int l = 0; l < NL; l++) {
        const __nv_bfloat16* iph = wph + (size_t)l * 2 * DI * DM;
        const __nv_bfloat16* ipl = wpl + (size_t)l * 2 * DI * DM;
        const __nv_bfloat16* xpj = wxh + (size_t)l * 128 * DI;
        const __nv_bfloat16* xpl2= wxl + (size_t)l * 128 * DI;
        const __nv_bfloat16* dth = wdh + (size_t)l * DI * DTR;
        const __nv_bfloat16* dtl = wdl + (size_t)l * DI * DTR;
        const __nv_bfloat16* ohh = woh + (size_t)l * DM * DI;
        const __nv_bfloat16* oll = wol + (size_t)l * DM * DI;
        const float* cw  = conv_w  + (size_t)l * DI * DC;
        const float* cb  = conv_b  + (size_t)l * DI;
        const float* dtb = dt_b    + (size_t)l * DI;
        const float* Dp  = D_param + (size_t)l * DI;
        const float* lg  = ln_g    + (size_t)l * DM;
        const float* lb  = ln_b    + (size_t)l * DM;

        // xz = h @ in_proj^T   [4096 x 4096], K=1024
        gemm_tc<<<dim3(2*DI/128, BATCH/128), blk, GEMM_SMEM>>>(
            hh, hl, DM/64, iph, ipl, DM/64, DM/64,
            nullptr, p_xz, 2*DI, nullptr, nullptr, 0);
        conv_silu_kernel<<<BATCH, 256>>>(cw, cb);
        // x_dbl = xc @ xproj^T  [4096 x 96], K=2048 (emits tiled hi/lo, N pad 128)
        gemm_tc<<<dim3(1, BATCH/128), blk, GEMM_SMEM>>>(
            xch, xcl, DI/64, xpj, xpl2, DI/64, DI/64,
            nullptr, p_xdbl, XD, xdh, xdl, 2);
        // dt_pre = x_dbl[:, :64] @ dt_w^T  [4096 x 2048], K=64
        gemm_tc<<<dim3(DI/128, BATCH/128), blk, GEMM_SMEM>>>(
            xdh, xdl, 2, dth, dtl, 1, 1,
            nullptr, p_dtp, DI, nullptr, nullptr, 0);
        gate_kernel<<<BATCH, 256>>>(dtb, Dp);
        // yo = y @ out_w^T  [4096 x 1024], K=2048
        gemm_tc<<<dim3(DM/128, BATCH/128), blk, GEMM_SMEM>>>(
            yh, yl, DI/64, ohh, oll, DI/64, DI/64,
            nullptr, p_yo, DM, nullptr, nullptr, 0);
        ln_res_kernel<<<BATCH, 256>>>(lg, lb);
    }

    // out = h @ outp_w^T + outp_b
    gemm_tc<<<dim3(1, BATCH/128), blk, GEMM_SMEM>>>(
        hh, hl, DM/64, wqh, wql, DM/64, DM/64,
        outp_b, out, OUT_DIM, nullptr, nullptr, 0);
    (void)in_sizes; (void)n_in; (void)out_size;
}

// round 7
// speedup vs baseline: 4.3138x; 1.1306x over previous
#include <cuda_runtime.h>
#include <cuda_bf16.h>
#include <cstdint>
#include <math.h>

// Problem constants
#define NL  4
#define DM  1024
#define DI  2048
#define DS  16
#define DC  4
#define DTR 64
#define IN_DIM  256
#define OUT_DIM 128
#define BATCH 4096
#define XD 96          // DTR + 2*DS

// ---------------------------------------------------------------------------
// fp32 scratch
// ---------------------------------------------------------------------------
__device__ float g_h   [BATCH * DM];
__device__ float g_xz  [BATCH * 2 * DI];
__device__ float g_xc  [BATCH * DI];
__device__ float g_xdbl[BATCH * XD];
__device__ float g_dtp [BATCH * DI];
__device__ float g_yo  [BATCH * DM];
__device__ float g_part[4 * BATCH * 128];   // split-K partials

// ---------------------------------------------------------------------------
// Tiled bf16 operands. Tile = 128 rows x 64 cols = 8192 elems = 16KB,
// SW128-swizzled internally, tiles contiguous: (rb*KT + kb)*8192 elems.
// ---------------------------------------------------------------------------
__device__ __align__(1024) __nv_bfloat16 t_x_hi [BATCH * IN_DIM], t_x_lo [BATCH * IN_DIM];
__device__ __align__(1024) __nv_bfloat16 t_h_hi [BATCH * DM],     t_h_lo [BATCH * DM];
__device__ __align__(1024) __nv_bfloat16 t_xc_hi[BATCH * DI],     t_xc_lo[BATCH * DI];
__device__ __align__(1024) __nv_bfloat16 t_xd_hi[BATCH * 128],    t_xd_lo[BATCH * 128];   // XD padded
__device__ __align__(1024) __nv_bfloat16 t_y_hi [BATCH * DI],     t_y_lo [BATCH * DI];

__device__ __align__(1024) __nv_bfloat16 t_wi_hi[DM * IN_DIM],       t_wi_lo[DM * IN_DIM];
__device__ __align__(1024) __nv_bfloat16 t_wp_hi[NL * 2 * DI * DM],  t_wp_lo[NL * 2 * DI * DM];
__device__ __align__(1024) __nv_bfloat16 t_wx_hi[NL * 128 * DI],     t_wx_lo[NL * 128 * DI];
__device__ __align__(1024) __nv_bfloat16 t_wd_hi[NL * DI * DTR],     t_wd_lo[NL * DI * DTR];
__device__ __align__(1024) __nv_bfloat16 t_wo_hi[NL * DM * DI],      t_wo_lo[NL * DM * DI];
__device__ __align__(1024) __nv_bfloat16 t_wq_hi[OUT_DIM * DM],      t_wq_lo[OUT_DIM * DM];

// ---------------------------------------------------------------------------
// Tiled addressing: element (row, col) of [R, Kpad], KT = Kpad/64.
// ---------------------------------------------------------------------------
__device__ __forceinline__ size_t tiled_off(int row, int col, int KT) {
    size_t tile = (size_t)((row >> 7) * KT + (col >> 6));
    uint32_t inner = (uint32_t)((row & 127) * 128)
                   + (((uint32_t)((col & 63) * 2)) ^ ((uint32_t)(row & 7) << 4));
    return tile * 8192 + (inner >> 1);
}

// ---------------------------------------------------------------------------
// PTX helpers
// ---------------------------------------------------------------------------
__device__ __forceinline__ uint32_t smem_u32(const void* p) {
    uint32_t a;
    asm("{ .reg .u64 t; cvta.to.shared.u64 t, %1; cvt.u32.u64 %0, t; }" : "=r"(a) : "l"(p));
    return a;
}
#define MBARRIER_INIT(a, c) \
    asm volatile("mbarrier.init.shared.b64 [%0], %1;" :: "r"((uint32_t)(a)), "r"((uint32_t)(c)) : "memory")
#define MBAR_EXPECT(a, n) \
    asm volatile("mbarrier.arrive.expect_tx.shared.b64 _, [%0], %1;" :: "r"((uint32_t)(a)), "r"((uint32_t)(n)) : "memory")
#define MBAR_ARRIVE(a) \
    asm volatile("mbarrier.arrive.shared.b64 _, [%0];" :: "r"((uint32_t)(a)) : "memory")
#define CP_BULK(sdst, gsrc, nbytes, bar) \
    asm volatile("cp.async.bulk.shared::cta.global.mbarrier::complete_tx::bytes [%0], [%1], %2, [%3];" \
                 :: "r"((uint32_t)(sdst)), "l"(gsrc), "r"((uint32_t)(nbytes)), "r"((uint32_t)(bar)) : "memory")
#define MBARRIER_WAIT_PARITY(mbar_smem_addr, phase_parity) do { \
    uint32_t _mbar = (uint32_t)(mbar_smem_addr); \
    uint32_t _parity = (uint32_t)(phase_parity); \
    uint32_t _done; \
    asm volatile("{\n\t.reg .pred p;\n\t" \
        "mbarrier.try_wait.parity.acquire.cta.shared::cta.b64 p, [%1], %2;\n\t" \
        "selp.b32 %0, 1, 0, p;\n\t}" : "=r"(_done) : "r"(_mbar), "r"(_parity) : "memory"); \
    if (!_done) { \
        asm volatile("{\n\t.reg .pred P1;\n\t" \
            "WAIT_LOOP_%=:\n\t" \
            "mbarrier.try_wait.parity.acquire.cta.shared::cta.b64 P1, [%0], %1, 0x989680;\n\t" \
            "@P1 bra.uni WAIT_DONE_%=;\n\t" \
            "bra.uni WAIT_LOOP_%=;\n\t" \
            "WAIT_DONE_%=:\n\t}" :: "r"(_mbar), "r"(_parity) : "memory"); \
    } \
} while (0)

__device__ __forceinline__ void ldsm4(uint32_t& r0, uint32_t& r1, uint32_t& r2, uint32_t& r3,
                                      uint32_t a) {
    asm volatile("ldmatrix.sync.aligned.m8n8.x4.shared.b16 {%0,%1,%2,%3}, [%4];"
                 : "=r"(r0), "=r"(r1), "=r"(r2), "=r"(r3) : "r"(a));
}
__device__ __forceinline__ void mma_bf16(float* c, const uint32_t* a, const uint32_t* b) {
    asm volatile("mma.sync.aligned.m16n8k16.row.col.f32.bf16.bf16.f32 "
                 "{%0,%1,%2,%3}, {%4,%5,%6,%7}, {%8,%9}, {%0,%1,%2,%3};"
                 : "+f"(c[0]), "+f"(c[1]), "+f"(c[2]), "+f"(c[3])
                 : "r"(a[0]), "r"(a[1]), "r"(a[2]), "r"(a[3]), "r"(b[0]), "r"(b[1]));
}

// ---------------------------------------------------------------------------
// bf16x3 GEMM, bulk-copy 3-stage pipeline, full/empty mbarrier (no mainloop
// __syncthreads). CTA 128x128, BK=64, 256 threads (8 warps, warp tile 64x32).
// blockIdx.z = K-slice (split-K): reads tiles [z*niter, (z+1)*niter), writes
// its partial to C + z*BATCH*N.
// ---------------------------------------------------------------------------
#define TILE_BYTES 16384
#define STAGE_BYTES (4 * TILE_BYTES)
#define NSTAGE 3
#define GEMM_SMEM (NSTAGE * STAGE_BYTES + 64)

__global__ __launch_bounds__(256, 1)
void gemm_tc(const __nv_bfloat16* __restrict__ Ah, const __nv_bfloat16* __restrict__ Al, int KTa,
             const __nv_bfloat16* __restrict__ Wh, const __nv_bfloat16* __restrict__ Wl, int KTb,
             int niter,
             const float* __restrict__ bias,
             float* __restrict__ C, int N,
             __nv_bfloat16* __restrict__ Chi, __nv_bfloat16* __restrict__ Clo, int NT)
{
    extern __shared__ char smem[];
    const uint32_t sbase = smem_u32(smem);
    const uint32_t sfull = sbase + NSTAGE * STAGE_BYTES;        // 3 x 8B
    const uint32_t sempt = sfull + NSTAGE * 8;                  // 3 x 8B

    const int tid  = threadIdx.x;
    const int wid  = tid >> 5;
    const int lane = tid & 31;
    const int rbA = blockIdx.y;
    const int rbB = blockIdx.x;
    const int kOff = blockIdx.z * niter;
    C += (size_t)blockIdx.z * BATCH * N;

    if (tid == 0) {
        #pragma unroll
        for (int s = 0; s < NSTAGE; s++) {
            MBARRIER_INIT(sfull + s * 8, 1);
            MBARRIER_INIT(sempt + s * 8, 8);
        }
        asm volatile("fence.proxy.async.shared::cta;" ::: "memory");
    }
    __syncthreads();

    const char* pAh = (const char*)Ah;
    const char* pAl = (const char*)Al;
    const char* pWh = (const char*)Wh;
    const char* pWl = (const char*)Wl;

    auto issue = [&](int kb, int s) {
        uint32_t st = sbase + s * STAGE_BYTES;
        uint32_t bar = sfull + s * 8;
        MBAR_EXPECT(bar, 4 * TILE_BYTES);
        size_t oa = ((size_t)(rbA * KTa + kOff + kb)) << 14;
        size_t ob = ((size_t)(rbB * KTb + kOff + kb)) << 14;
        CP_BULK(st,                  pAh + oa, TILE_BYTES, bar);
        CP_BULK(st + TILE_BYTES,     pAl + oa, TILE_BYTES, bar);
        CP_BULK(st + 2 * TILE_BYTES, pWh + ob, TILE_BYTES, bar);
        CP_BULK(st + 3 * TILE_BYTES, pWl + ob, TILE_BYTES, bar);
    };

    if (tid == 0) {
        #pragma unroll
        for (int s = 0; s < NSTAGE; s++)
            if (s < niter) issue(s, s);
    }

    // ldmatrix lane constants
    const int lm = lane >> 3;
    const int lr = lane & 7;
    const int wm = (wid >> 2) * 64;
    const int wn = (wid & 3) * 32;
    const uint32_t xmask = (uint32_t)lr << 4;
    const uint32_t arow = (uint32_t)(wm + (lm & 1) * 8 + lr) * 128;
    const uint32_t aseg = (uint32_t)(lm >> 1) * 16;
    const uint32_t brow = (uint32_t)(wn + (lm >> 1) * 8 + lr) * 128;
    const uint32_t bseg = (uint32_t)(lm & 1) * 16;

    float acc[4][4][4];
    #pragma unroll
    for (int i = 0; i < 4; i++)
        #pragma unroll
        for (int j = 0; j < 4; j++)
            #pragma unroll
            for (int q = 0; q < 4; q++) acc[i][j][q] = 0.f;

    for (int kb = 0; kb < niter; kb++) {
        const int s = kb % NSTAGE;
        const int ph = (kb / NSTAGE) & 1;
        MBARRIER_WAIT_PARITY(sfull + s * 8, ph);
        uint32_t st  = sbase + s * STAGE_BYTES;
        uint32_t sAh = st;
        uint32_t sAl = st + TILE_BYTES;
        uint32_t sBh = st + 2 * TILE_BYTES;
        uint32_t sBl = st + 3 * TILE_BYTES;

        #pragma unroll
        for (int kk = 0; kk < 4; kk++) {
            uint32_t ka  = ((uint32_t)(kk * 32) + aseg) ^ xmask;
            uint32_t kbo = ((uint32_t)(kk * 32) + bseg) ^ xmask;
            uint32_t bh[4][2], bl[4][2];
            #pragma unroll
            for (int p = 0; p < 2; p++) {
                ldsm4(bh[2*p][0], bh[2*p][1], bh[2*p+1][0], bh[2*p+1][1],
                      sBh + brow + p * 2048 + kbo);
                ldsm4(bl[2*p][0], bl[2*p][1], bl[2*p+1][0], bl[2*p+1][1],
                      sBl + brow + p * 2048 + kbo);
            }
            #pragma unroll
            for (int mi = 0; mi < 4; mi++) {
                uint32_t ah[4], al[4];
                ldsm4(ah[0], ah[1], ah[2], ah[3], sAh + arow + mi * 2048 + ka);
                ldsm4(al[0], al[1], al[2], al[3], sAl + arow + mi * 2048 + ka);
                #pragma unroll
                for (int ni = 0; ni < 4; ni++) {
                    mma_bf16(acc[mi][ni], ah, bh[ni]);
                    mma_bf16(acc[mi][ni], ah, bl[ni]);
                    mma_bf16(acc[mi][ni], al, bh[ni]);
                }
            }
        }
        // this warp is done reading stage s
        if (lane == 0) MBAR_ARRIVE(sempt + s * 8);
        // producer: refill stage s once all 8 warps have consumed it
        if (tid == 0 && kb + NSTAGE < niter) {
            MBARRIER_WAIT_PARITY(sempt + s * 8, ph);
            issue(kb + NSTAGE, s);
        }
    }

    // ---- epilogue ----
    const int g = lane >> 2, t4 = lane & 3;
    const int bm = rbA * 128, bn = rbB * 128;
    #pragma unroll
    for (int mi = 0; mi < 4; mi++) {
        #pragma unroll
        for (int ni = 0; ni < 4; ni++) {
            int col = bn + wn + ni * 8 + t4 * 2;
            float b0 = 0.f, b1 = 0.f;
            if (bias && col < N) { b0 = bias[col]; b1 = bias[col + 1]; }
            #pragma unroll
            for (int hrow = 0; hrow < 2; hrow++) {
                int row = bm + wm + mi * 16 + g + hrow * 8;
                float v0 = acc[mi][ni][hrow * 2 + 0] + b0;
                float v1 = acc[mi][ni][hrow * 2 + 1] + b1;
                if (col < N)
                    *(float2*)(C + (size_t)row * N + col) = make_float2(v0, v1);
                if (Chi) {
                    size_t to = tiled_off(row, col, NT);
                    __nv_bfloat16 h0 = __float2bfloat16(v0), h1 = __float2bfloat16(v1);
                    __nv_bfloat162 ph2 = {h0, h1};
                    __nv_bfloat162 pl2 = {__float2bfloat16(v0 - __bfloat162float(h0)),
                                          __float2bfloat16(v1 - __bfloat162float(h1))};
                    *(__nv_bfloat162*)(Chi + to) = ph2;
                    *(__nv_bfloat162*)(Clo + to) = pl2;
                }
            }
        }
    }
}

// ---------------------------------------------------------------------------
// Split-K reduce: xdbl = sum of 4 partials; emit fp32 [B, XD] + tiled hi/lo
// for dt columns (0..63). One block per row, 128 threads.
// ---------------------------------------------------------------------------
__global__ void reduce_xdbl_kernel()
{
    int row = blockIdx.x;
    int t = threadIdx.x;
    float v = g_part[(size_t)row * 128 + t]
            + g_part[(size_t)BATCH * 128     + (size_t)row * 128 + t]
            + g_part[(size_t)BATCH * 128 * 2 + (size_t)row * 128 + t]
            + g_part[(size_t)BATCH * 128 * 3 + (size_t)row * 128 + t];
    if (t < XD) g_xdbl[(size_t)row * XD + t] = v;
    if (t < DTR) {
        __nv_bfloat16 h = __float2bfloat16(v);
        size_t to = tiled_off(row, t, 2);
        t_xd_hi[to] = h;
        t_xd_lo[to] = __float2bfloat16(v - __bfloat162float(h));
    }
}

// ---------------------------------------------------------------------------
// Split-K reduce for final projection: out = sum partials + bias
// ---------------------------------------------------------------------------
__global__ void reduce_out_kernel(const float* __restrict__ bias,
                                  float* __restrict__ out)
{
    int row = blockIdx.x;
    int t = threadIdx.x;     // 128 = OUT_DIM
    float v = bias[t]
            + g_part[(size_t)row * 128 + t]
            + g_part[(size_t)BATCH * 128     + (size_t)row * 128 + t]
            + g_part[(size_t)BATCH * 128 * 2 + (size_t)row * 128 + t]
            + g_part[(size_t)BATCH * 128 * 3 + (size_t)row * 128 + t];
    out[(size_t)row * OUT_DIM + t] = v;
}

// ---------------------------------------------------------------------------
// fp32 [R,K] -> tiled+swizzled bf16 hi/lo
// ---------------------------------------------------------------------------
__global__ void cvt_tiled(const float* __restrict__ src,
                          __nv_bfloat16* __restrict__ hi,
                          __nv_bfloat16* __restrict__ lo,
                          int R, int k8, int KT)
{
    int idx = blockIdx.x * 256 + threadIdx.x;
    if (idx >= R * k8) return;
    int row = idx / k8;
    int k = (idx - row * k8) * 8;
    const float4* s = (const float4*)(src + (size_t)row * (k8 * 8) + k);
    float4 v0 = s[0], v1 = s[1];
    float f[8] = {v0.x, v0.y, v0.z, v0.w, v1.x, v1.y, v1.z, v1.w};
    uint32_t ph[4], pl[4];
    #pragma unroll
    for (int j = 0; j < 4; j++) {
        float a = f[2*j], b = f[2*j+1];
        __nv_bfloat16 ha = __float2bfloat16(a), hb = __float2bfloat16(b);
        __nv_bfloat162 vh = {ha, hb};
        __nv_bfloat162 vl = {__float2bfloat16(a - __bfloat162float(ha)),
                             __float2bfloat16(b - __bfloat162float(hb))};
        ph[j] = *(uint32_t*)&vh;
        pl[j] = *(uint32_t*)&vl;
    }
    size_t to = tiled_off(row, k, KT);
    *(uint4*)(hi + to) = make_uint4(ph[0], ph[1], ph[2], ph[3]);
    *(uint4*)(lo + to) = make_uint4(pl[0], pl[1], pl[2], pl[3]);
}

// ---------------------------------------------------------------------------
// xc = silu(conv_b + xz[:, :DI] * conv_w[:, DC-1]); fp32 + tiled hi/lo
// ---------------------------------------------------------------------------
__global__ void conv_silu_kernel(const float* __restrict__ cw,
                                 const float* __restrict__ cb)
{
    int idx = blockIdx.x * 256 + threadIdx.x;
    int b = idx >> 8;
    int e = (idx & 255) * 8;
    const float4* s = (const float4*)(g_xz + (size_t)b * (2 * DI) + e);
    float4 v0 = s[0], v1 = s[1];
    float f[8] = {v0.x, v0.y, v0.z, v0.w, v1.x, v1.y, v1.z, v1.w};
    float r[8];
    #pragma unroll
    for (int j = 0; j < 8; j++) {
        float c = cb[e + j] + f[j] * cw[(e + j) * DC + (DC - 1)];
        r[j] = c / (1.f + expf(-c));
    }
    float4* d = (float4*)(g_xc + (size_t)b * DI + e);
    d[0] = make_float4(r[0], r[1], r[2], r[3]);
    d[1] = make_float4(r[4], r[5], r[6], r[7]);
    uint32_t ph[4], pl[4];
    #pragma unroll
    for (int j = 0; j < 4; j++) {
        __nv_bfloat16 ha = __float2bfloat16(r[2*j]), hb = __float2bfloat16(r[2*j+1]);
        __nv_bfloat162 vh = {ha, hb};
        __nv_bfloat162 vl = {__float2bfloat16(r[2*j]   - __bfloat162float(ha)),
                             __float2bfloat16(r[2*j+1] - __bfloat162float(hb))};
        ph[j] = *(uint32_t*)&vh; pl[j] = *(uint32_t*)&vl;
    }
    size_t to = tiled_off(b, e, DI / 64);
    *(uint4*)(t_xc_hi + to) = make_uint4(ph[0], ph[1], ph[2], ph[3]);
    *(uint4*)(t_xc_lo + to) = make_uint4(pl[0], pl[1], pl[2], pl[3]);
}

// ---------------------------------------------------------------------------
// y = xc * (softplus(dtp+dtb)*dot(B,C) + Dp) * silu(z) -> tiled hi/lo
// ---------------------------------------------------------------------------
__global__ void gate_kernel(const float* __restrict__ dtb,
                            const float* __restrict__ Dp)
{
    int b = blockIdx.x;
    int t = threadIdx.x;
    __shared__ float sbc;
    if (t < 32) {
        float p = 0.f;
        if (t < DS)
            p = g_xdbl[(size_t)b * XD + DTR + t] * g_xdbl[(size_t)b * XD + DTR + DS + t];
        #pragma unroll
        for (int o = 16; o; o >>= 1) p += __shfl_down_sync(0xffffffffu, p, o);
        if (t == 0) sbc = p;
    }
    __syncthreads();
    float bc = sbc;
    int e = t * 8;
    const float4* sd = (const float4*)(g_dtp + (size_t)b * DI + e);
    const float4* sx = (const float4*)(g_xc  + (size_t)b * DI + e);
    const float4* sz = (const float4*)(g_xz  + (size_t)b * (2 * DI) + DI + e);
    float4 d0 = sd[0], d1 = sd[1], x0 = sx[0], x1 = sx[1], z0 = sz[0], z1 = sz[1];
    float dv[8] = {d0.x,d0.y,d0.z,d0.w,d1.x,d1.y,d1.z,d1.w};
    float xv[8] = {x0.x,x0.y,x0.z,x0.w,x1.x,x1.y,x1.z,x1.w};
    float zv[8] = {z0.x,z0.y,z0.z,z0.w,z1.x,z1.y,z1.z,z1.w};
    float y[8];
    #pragma unroll
    for (int j = 0; j < 8; j++) {
        float dp = dv[j] + dtb[e + j];
        float dt = (dp > 20.f) ? dp : log1pf(expf(dp));
        float sz2 = zv[j] / (1.f + expf(-zv[j]));
        y[j] = xv[j] * (dt * bc + Dp[e + j]) * sz2;
    }
    uint32_t ph[4], pl[4];
    #pragma unroll
    for (int j = 0; j < 4; j++) {
        __nv_bfloat16 ha = __float2bfloat16(y[2*j]), hb = __float2bfloat16(y[2*j+1]);
        __nv_bfloat162 vh = {ha, hb};
        __nv_bfloat162 vl = {__float2bfloat16(y[2*j]   - __bfloat162float(ha)),
                             __float2bfloat16(y[2*j+1] - __bfloat162float(hb))};
        ph[j] = *(uint32_t*)&vh; pl[j] = *(uint32_t*)&vl;
    }
    size_t to = tiled_off(b, e, DI / 64);
    *(uint4*)(t_y_hi + to) = make_uint4(ph[0], ph[1], ph[2], ph[3]);
    *(uint4*)(t_y_lo + to) = make_uint4(pl[0], pl[1], pl[2], pl[3]);
}

// ---------------------------------------------------------------------------
// h += LN(yo)*g + b; fp32 h + tiled hi/lo
// ---------------------------------------------------------------------------
__global__ void ln_res_kernel(const float* __restrict__ gam,
                              const float* __restrict__ bet)
{
    int b = blockIdx.x;
    int t = threadIdx.x;
    __shared__ float sa[8], sbs[8], smu, sinv;
    int d = t * 4;
    float4 v4 = *(const float4*)(g_yo + (size_t)b * DM + d);
    float vv[4] = {v4.x, v4.y, v4.z, v4.w};
    float s = vv[0] + vv[1] + vv[2] + vv[3];
    float s2 = vv[0]*vv[0] + vv[1]*vv[1] + vv[2]*vv[2] + vv[3]*vv[3];
    int lane = t & 31, w = t >> 5;
    #pragma unroll
    for (int o = 16; o; o >>= 1) {
        s  += __shfl_down_sync(0xffffffffu, s,  o);
        s2 += __shfl_down_sync(0xffffffffu, s2, o);
    }
    if (lane == 0) { sa[w] = s; sbs[w] = s2; }
    __syncthreads();
    if (w == 0) {
        s  = (lane < 8) ? sa[lane] : 0.f;
        s2 = (lane < 8) ? sbs[lane] : 0.f;
        #pragma unroll
        for (int o = 4; o; o >>= 1) {
            s  += __shfl_down_sync(0xffffffffu, s,  o);
            s2 += __shfl_down_sync(0xffffffffu, s2, o);
        }
        if (lane == 0) {
            float mu = s / DM;
            float var = s2 / DM - mu * mu;
            smu = mu;
            sinv = rsqrtf(var + 1e-5f);
        }
    }
    __syncthreads();
    float mu = smu, inv = sinv;
    float hv[4];
    #pragma unroll
    for (int j = 0; j < 4; j++) {
        size_t o = (size_t)b * DM + d + j;
        hv[j] = g_h[o] + (vv[j] - mu) * inv * gam[d + j] + bet[d + j];
        g_h[o] = hv[j];
    }
    uint32_t ph[2], pl[2];
    #pragma unroll
    for (int j = 0; j < 2; j++) {
        __nv_bfloat16 ha = __float2bfloat16(hv[2*j]), hb = __float2bfloat16(hv[2*j+1]);
        __nv_bfloat162 vh = {ha, hb};
        __nv_bfloat162 vl = {__float2bfloat16(hv[2*j]   - __bfloat162float(ha)),
                             __float2bfloat16(hv[2*j+1] - __bfloat162float(hb))};
        ph[j] = *(uint32_t*)&vh; pl[j] = *(uint32_t*)&vl;
    }
    size_t to = tiled_off(b, d, DM / 64);
    *(uint2*)(t_h_hi + to) = make_uint2(ph[0], ph[1]);
    *(uint2*)(t_h_lo + to) = make_uint2(pl[0], pl[1]);
}

// ---------------------------------------------------------------------------
// Host launcher
// ---------------------------------------------------------------------------
extern "C" void kernel_launch(void* const* d_in, const int* in_sizes, int n_in,
                              void* d_out, int out_size)
{
    const float* x        = (const float*)d_in[0];
    const float* inp_w    = (const float*)d_in[1];
    const float* inp_b    = (const float*)d_in[2];
    const float* in_proj  = (const float*)d_in[3];
    const float* conv_w   = (const float*)d_in[4];
    const float* conv_b   = (const float*)d_in[5];
    const float* xproj_w  = (const float*)d_in[6];
    const float* dt_w     = (const float*)d_in[7];
    const float* dt_b     = (const float*)d_in[8];
    // d_in[9] = A_log : dead (h0 == 0, single scan step)
    const float* D_param  = (const float*)d_in[10];
    const float* out_w    = (const float*)d_in[11];
    const float* ln_g     = (const float*)d_in[12];
    const float* ln_b     = (const float*)d_in[13];
    const float* outp_w   = (const float*)d_in[14];
    const float* outp_b   = (const float*)d_in[15];
    float* out = (float*)d_out;

    float *p_h, *p_xz, *p_dtp, *p_yo, *p_part;
    cudaGetSymbolAddress((void**)&p_h,    g_h);
    cudaGetSymbolAddress((void**)&p_xz,   g_xz);
    cudaGetSymbolAddress((void**)&p_dtp,  g_dtp);
    cudaGetSymbolAddress((void**)&p_yo,   g_yo);
    cudaGetSymbolAddress((void**)&p_part, g_part);

    __nv_bfloat16 *xh, *xl, *hh, *hl, *xch, *xcl, *xdh, *xdl, *yh, *yl;
    cudaGetSymbolAddress((void**)&xh,  t_x_hi);  cudaGetSymbolAddress((void**)&xl,  t_x_lo);
    cudaGetSymbolAddress((void**)&hh,  t_h_hi);  cudaGetSymbolAddress((void**)&hl,  t_h_lo);
    cudaGetSymbolAddress((void**)&xch, t_xc_hi); cudaGetSymbolAddress((void**)&xcl, t_xc_lo);
    cudaGetSymbolAddress((void**)&xdh, t_xd_hi); cudaGetSymbolAddress((void**)&xdl, t_xd_lo);
    cudaGetSymbolAddress((void**)&yh,  t_y_hi);  cudaGetSymbolAddress((void**)&yl,  t_y_lo);

    __nv_bfloat16 *wih, *wil, *wph, *wpl, *wxh, *wxl, *wdh, *wdl, *woh, *wol, *wqh, *wql;
    cudaGetSymbolAddress((void**)&wih, t_wi_hi); cudaGetSymbolAddress((void**)&wil, t_wi_lo);
    cudaGetSymbolAddress((void**)&wph, t_wp_hi); cudaGetSymbolAddress((void**)&wpl, t_wp_lo);
    cudaGetSymbolAddress((void**)&wxh, t_wx_hi); cudaGetSymbolAddress((void**)&wxl, t_wx_lo);
    cudaGetSymbolAddress((void**)&wdh, t_wd_hi); cudaGetSymbolAddress((void**)&wdl, t_wd_lo);
    cudaGetSymbolAddress((void**)&woh, t_wo_hi); cudaGetSymbolAddress((void**)&wol, t_wo_lo);
    cudaGetSymbolAddress((void**)&wqh, t_wq_hi); cudaGetSymbolAddress((void**)&wql, t_wq_lo);

    cudaFuncSetAttribute(gemm_tc, cudaFuncAttributeMaxDynamicSharedMemorySize, GEMM_SMEM);

    auto cvt = [](const float* s, __nv_bfloat16* h, __nv_bfloat16* l, int R, int K) {
        int n = R * (K / 8);
        cvt_tiled<<<(n + 255) / 256, 256>>>(s, h, l, R, K / 8, K / 64);
    };
    cvt(x,       xh,  xl,  BATCH, IN_DIM);
    cvt(inp_w,   wih, wil, DM, IN_DIM);
    cvt(in_proj, wph, wpl, NL * 2 * DI, DM);
    for (int l = 0; l < NL; l++)
        cvt(xproj_w + (size_t)l * XD * DI, wxh + (size_t)l * 128 * DI,
            wxl + (size_t)l * 128 * DI, XD, DI);
    cvt(dt_w,    wdh, wdl, NL * DI, DTR);
    cvt(out_w,   woh, wol, NL * DM, DI);
    cvt(outp_w,  wqh, wql, OUT_DIM, DM);

    dim3 blk(256);

    // h = x @ inp_w^T + inp_b  (emits tiled hi/lo)
    gemm_tc<<<dim3(DM/128, BATCH/128, 1), blk, GEMM_SMEM>>>(
        xh, xl, IN_DIM/64, wih, wil, IN_DIM/64, IN_DIM/64,
        inp_b, p_h, DM, hh, hl, DM/64);

    for (int l = 0; l < NL; l++) {
        const __nv_bfloat16* iph = wph + (size_t)l * 2 * DI * DM;
        const __nv_bfloat16* ipl = wpl + (size_t)l * 2 * DI * DM;
        const __nv_bfloat16* xpj = wxh + (size_t)l * 128 * DI;
        const __nv_bfloat16* xpl2= wxl + (size_t)l * 128 * DI;
        const __nv_bfloat16* dth = wdh + (size_t)l * DI * DTR;
        const __nv_bfloat16* dtl = wdl + (size_t)l * DI * DTR;
        const __nv_bfloat16* ohh = woh + (size_t)l * DM * DI;
        const __nv_bfloat16* oll = wol + (size_t)l * DM * DI;
        const float* cw  = conv_w  + (size_t)l * DI * DC;
        const float* cb  = conv_b  + (size_t)l * DI;
        const float* dtb = dt_b    + (size_t)l * DI;
        const float* Dp  = D_param + (size_t)l * DI;
        const float* lg  = ln_g    + (size_t)l * DM;
        const float* lb  = ln_b    + (size_t)l * DM;

        // xz = h @ in_proj^T   [4096 x 4096], K=1024
        gemm_tc<<<dim3(2*DI/128, BATCH/128, 1), blk, GEMM_SMEM>>>(
            hh, hl, DM/64, iph, ipl, DM/64, DM/64,
            nullptr, p_xz, 2*DI, nullptr, nullptr, 0);
        conv_silu_kernel<<<BATCH, 256>>>(cw, cb);
        // x_dbl partials: split-K x4 (each K=512), 128 CTAs
        gemm_tc<<<dim3(1, BATCH/128, 4), blk, GEMM_SMEM>>>(
            xch, xcl, DI/64, xpj, xpl2, DI/64, (DI/64)/4,
            nullptr, p_part, 128, nullptr, nullptr, 0);
        reduce_xdbl_kernel<<<BATCH, 128>>>();
        // dt_pre = x_dbl[:, :64] @ dt_w^T  [4096 x 2048], K=64
        gemm_tc<<<dim3(DI/128, BATCH/128, 1), blk, GEMM_SMEM>>>(
            xdh, xdl, 2, dth, dtl, 1, 1,
            nullptr, p_dtp, DI, nullptr, nullptr, 0);
        gate_kernel<<<BATCH, 256>>>(dtb, Dp);
        // yo = y @ out_w^T  [4096 x 1024], K=2048
        gemm_tc<<<dim3(DM/128, BATCH/128, 1), blk, GEMM_SMEM>>>(
            yh, yl, DI/64, ohh, oll, DI/64, DI/64,
            nullptr, p_yo, DM, nullptr, nullptr, 0);
        ln_res_kernel<<<BATCH, 256>>>(lg, lb);
    }

    // out partials: split-K x4 (each K=256), then reduce + bias
    gemm_tc<<<dim3(1, BATCH/128, 4), blk, GEMM_SMEM>>>(
        hh, hl, DM/64, wqh, wql, DM/64, (DM/64)/4,
        nullptr, p_part, 128, nullptr, nullptr, 0);
    reduce_out_kernel<<<BATCH, 128>>>(outp_b, out);
    (void)in_sizes; (void)n_in; (void)out_size;
}